// round 6
// baseline (speedup 1.0000x reference)
#include <cuda_runtime.h>

#define N_NODES 50000
#define N_EDGES 200000
#define HDIM 32
#define T_ITERS 8

// ---------------- scratch (device globals: no allocation allowed) ----------
__device__ float g_A[(size_t)N_EDGES * 1024];   // A per edge, fp32, layout [e][j][i]
__device__ float g_m[N_NODES * HDIM];           // aggregated messages
__device__ float g_x0[N_NODES * HDIM];          // ping
__device__ float g_x1[N_NODES * HDIM];          // pong

// ---------------- packed f32x2 helpers (sm_100+) ----------------
__device__ __forceinline__ unsigned long long fma2(unsigned long long a,
                                                   unsigned long long b,
                                                   unsigned long long c) {
    unsigned long long d;
    asm("fma.rn.f32x2 %0, %1, %2, %3;" : "=l"(d) : "l"(a), "l"(b), "l"(c));
    return d;
}
__device__ __forceinline__ unsigned long long pack2(float x, float y) {
    unsigned long long d;
    asm("mov.b64 %0, {%1, %2};" : "=l"(d) : "f"(x), "f"(y));
    return d;
}
__device__ __forceinline__ float2 unpack2(unsigned long long v) {
    float2 r;
    asm("mov.b64 {%0, %1}, %2;" : "=f"(r.x), "=f"(r.y) : "l"(v));
    return r;
}
__device__ __forceinline__ float sigmoidf_(float v) {
    return 1.0f / (1.0f + __expf(-v));
}

// ============================================================
// copy input x -> g_x0, zero g_m
// ============================================================
__global__ void copy_x_kernel(const float* __restrict__ x) {
    int i = blockIdx.x * blockDim.x + threadIdx.x;
    if (i < N_NODES * HDIM / 4) {
        ((float4*)g_x0)[i] = ((const float4*)x)[i];
        ((float4*)g_m)[i]  = make_float4(0.f, 0.f, 0.f, 0.f);
    }
}

// ============================================================
// Edge MLP (unchanged — proven):
//   hid = relu(edge_data @ W1^T + b1)            [E,64]
//   A   = relu(hid @ W2^T + b2)                  [E,1024], fp32, stored [e][j][i]
// ============================================================
__global__ __launch_bounds__(256, 2) void edge_mlp_kernel(
    const float* __restrict__ ed, const float* __restrict__ W1,
    const float* __restrict__ b1, const float* __restrict__ W2,
    const float* __restrict__ b2)
{
    __shared__ float s_h2[64 * 132];  // [k][2e]
    __shared__ float s_w[64 * 128];   // [k][swizzled q]

    const int tid = threadIdx.x;
    const size_t e0 = (size_t)blockIdx.x * 64;

    // ---------- phase 1: hid (duplicated pairs into s_h2) ----------
    {
        const int o  = tid & 63;
        const int eg = (tid >> 6) * 16;
        float w[16];
        #pragma unroll
        for (int q = 0; q < 4; q++) {
            float4 v = __ldg((const float4*)(W1 + o * 16) + q);
            w[4*q+0] = v.x; w[4*q+1] = v.y; w[4*q+2] = v.z; w[4*q+3] = v.w;
        }
        const float bb = __ldg(b1 + o);
        #pragma unroll 4
        for (int ii = 0; ii < 16; ii++) {
            const int e = eg + ii;
            const float4* ep = (const float4*)(ed + (e0 + e) * 16);
            float acc = bb;
            #pragma unroll
            for (int q = 0; q < 4; q++) {
                float4 v = __ldg(ep + q);
                acc += v.x * w[4*q+0] + v.y * w[4*q+1]
                     + v.z * w[4*q+2] + v.w * w[4*q+3];
            }
            acc = fmaxf(acc, 0.f);
            s_h2[o * 132 + 2 * e + 0] = acc;
            s_h2[o * 132 + 2 * e + 1] = acc;
        }
    }
    __syncthreads();

    const int m  = tid & 15;
    const int ey = (tid >> 4) * 4;

    for (int qt = 0; qt < 8; qt++) {
        if (qt) __syncthreads();

        #pragma unroll
        for (int r = 0; r < 8; r++) {
            const int slot = tid + r * 256;
            const int q   = slot >> 4;
            const int k4  = slot & 15;
            const int qg  = qt * 128 + q;
            const int o   = ((qg & 31) << 5) | (qg >> 5);
            float4 v = __ldg((const float4*)(W2 + (size_t)o * 64) + k4);
            const int qlo = q & 3;
            const int qc  = q >> 2;
            #pragma unroll
            for (int c = 0; c < 4; c++) {
                const int k = 4 * k4 + c;
                const int p = qc ^ ((k >> 2) & 7);
                const float vv = (c == 0) ? v.x : (c == 1) ? v.y : (c == 2) ? v.z : v.w;
                s_w[k * 128 + 4 * p + qlo] = vv;
            }
        }
        __syncthreads();

        float bq[8];
        #pragma unroll
        for (int c = 0; c < 8; c++) {
            const int qg = qt * 128 + ((c < 4) ? (4 * m + c) : (64 + 4 * m + (c - 4)));
            const int o  = ((qg & 31) << 5) | (qg >> 5);
            bq[c] = __ldg(b2 + o);
        }
        unsigned long long acc[4][4];
        {
            const unsigned long long p0 = pack2(bq[0], bq[1]);
            const unsigned long long p1 = pack2(bq[2], bq[3]);
            const unsigned long long p2 = pack2(bq[4], bq[5]);
            const unsigned long long p3 = pack2(bq[6], bq[7]);
            #pragma unroll
            for (int je = 0; je < 4; je++) {
                acc[je][0] = p0; acc[je][1] = p1; acc[je][2] = p2; acc[je][3] = p3;
            }
        }

        #pragma unroll 8
        for (int k = 0; k < 64; k++) {
            const int s = (k >> 2) & 7;
            const float* wrow = s_w + k * 128;
            const ulonglong2 wA = *(const ulonglong2*)(wrow + 4 * (m ^ s));
            const ulonglong2 wB = *(const ulonglong2*)(wrow + 4 * ((m ^ s) + 16));
            const float* hrow = s_h2 + k * 132 + 2 * ey;
            const ulonglong2 hA = *(const ulonglong2*)(hrow);
            const ulonglong2 hB = *(const ulonglong2*)(hrow + 4);
            acc[0][0] = fma2(wA.x, hA.x, acc[0][0]);
            acc[0][1] = fma2(wA.y, hA.x, acc[0][1]);
            acc[0][2] = fma2(wB.x, hA.x, acc[0][2]);
            acc[0][3] = fma2(wB.y, hA.x, acc[0][3]);
            acc[1][0] = fma2(wA.x, hA.y, acc[1][0]);
            acc[1][1] = fma2(wA.y, hA.y, acc[1][1]);
            acc[1][2] = fma2(wB.x, hA.y, acc[1][2]);
            acc[1][3] = fma2(wB.y, hA.y, acc[1][3]);
            acc[2][0] = fma2(wA.x, hB.x, acc[2][0]);
            acc[2][1] = fma2(wA.y, hB.x, acc[2][1]);
            acc[2][2] = fma2(wB.x, hB.x, acc[2][2]);
            acc[2][3] = fma2(wB.y, hB.x, acc[2][3]);
            acc[3][0] = fma2(wA.x, hB.y, acc[3][0]);
            acc[3][1] = fma2(wA.y, hB.y, acc[3][1]);
            acc[3][2] = fma2(wB.x, hB.y, acc[3][2]);
            acc[3][3] = fma2(wB.y, hB.y, acc[3][3]);
        }

        #pragma unroll
        for (int je = 0; je < 4; je++) {
            float* base = g_A + (e0 + ey + je) * 1024 + qt * 128;
            const float2 a0 = unpack2(acc[je][0]);
            const float2 a1 = unpack2(acc[je][1]);
            const float2 a2 = unpack2(acc[je][2]);
            const float2 a3 = unpack2(acc[je][3]);
            *(float4*)(base + 4 * m) =
                make_float4(fmaxf(a0.x, 0.f), fmaxf(a0.y, 0.f),
                            fmaxf(a1.x, 0.f), fmaxf(a1.y, 0.f));
            *(float4*)(base + 64 + 4 * m) =
                make_float4(fmaxf(a2.x, 0.f), fmaxf(a2.y, 0.f),
                            fmaxf(a3.x, 0.f), fmaxf(a3.y, 0.f));
        }
    }
}

// ============================================================
// Message pass: warp per edge. A read with streaming hint (zero reuse).
// ============================================================
__global__ __launch_bounds__(256) void msg_kernel(const int* __restrict__ edges, int t) {
    const float* __restrict__ xc = (t & 1) ? g_x1 : g_x0;

    const int warp = (blockIdx.x * blockDim.x + threadIdx.x) >> 5;
    const int lane = threadIdx.x & 31;
    if (warp >= N_EDGES) return;

    const int src = __ldg(edges + 2 * warp);
    const int dst = __ldg(edges + 2 * warp + 1);

    const float xv = __ldg(xc + (size_t)src * HDIM + lane);
    const float* Ap = g_A + (size_t)warp * 1024 + lane;

    float acc = 0.f;
    #pragma unroll
    for (int j = 0; j < 32; j++) {
        const float a  = __ldcs(Ap + j * 32);   // streaming: evict-first
        const float xj = __shfl_sync(0xffffffffu, xv, j);
        acc = fmaf(a, xj, acc);
    }

    atomicAdd(g_m + (size_t)src * HDIM + lane, acc);
    if (src != dst) atomicAdd(g_m + (size_t)dst * HDIM + lane, acc);
}

// ============================================================
// GRU cell: 2 threads per node, each computes 16 of the 32 outputs.
// 128-thread blocks; weights + biases in smem; x/m packed u64 in regs.
// Doubles the resident-warp count vs 1-thread-per-node (grid 782 vs 391)
// and halves per-thread latency exposure. Outputs are independent across
// the split (gates couple only along k). Also zeroes g_m for next iter.
// ============================================================
__global__ __launch_bounds__(128, 4) void gru_kernel(
    const float* __restrict__ W_ih, const float* __restrict__ W_hh,
    const float* __restrict__ b_ih, const float* __restrict__ b_hh,
    float* __restrict__ dout, int t)
{
    __shared__ float s_wih[96 * 64];
    __shared__ float s_whh[96 * 32];
    __shared__ float s_bih[96];
    __shared__ float s_bhh[96];

    const float* __restrict__ xc = (t & 1) ? g_x1 : g_x0;
    float* __restrict__ xo = (t == T_ITERS - 1) ? dout : ((t & 1) ? g_x0 : g_x1);

    for (int idx = threadIdx.x; idx < 96 * 64 / 4; idx += 128)
        ((float4*)s_wih)[idx] = __ldg((const float4*)W_ih + idx);
    for (int idx = threadIdx.x; idx < 96 * 32 / 4; idx += 128)
        ((float4*)s_whh)[idx] = __ldg((const float4*)W_hh + idx);
    if (threadIdx.x < 96) {
        s_bih[threadIdx.x] = __ldg(b_ih + threadIdx.x);
        s_bhh[threadIdx.x] = __ldg(b_hh + threadIdx.x);
    }
    __syncthreads();

    const int gidx = blockIdx.x * 128 + threadIdx.x;
    const int n    = gidx >> 1;        // node
    const int half = gidx & 1;         // output half: [half*16, half*16+16)
    const bool valid = (n < N_NODES);
    const int nn_ = valid ? n : (N_NODES - 1);

    // load x, m as packed pairs; zero m for next iteration (half 0 only)
    unsigned long long xp[16], mp[16];
    {
        const float4* xq = (const float4*)(xc + (size_t)nn_ * HDIM);
        float4* mq = (float4*)(g_m + (size_t)nn_ * HDIM);
        #pragma unroll
        for (int i = 0; i < 8; i++) {
            float4 v = __ldg(xq + i);
            xp[2*i]   = pack2(v.x, v.y);
            xp[2*i+1] = pack2(v.z, v.w);
            float4 u = mq[i];
            mp[2*i]   = pack2(u.x, u.y);
            mp[2*i+1] = pack2(u.z, u.w);
        }
        if (valid && half == 0) {
            #pragma unroll
            for (int i = 0; i < 8; i++) mq[i] = make_float4(0.f, 0.f, 0.f, 0.f);
        }
    }

    const int obase = half * 16;

    #pragma unroll 4
    for (int oc = 0; oc < 8; oc++) {
        const int ob = obase + 2 * oc;
        unsigned long long a_ir[2], a_iz[2], a_in[2], a_hr[2], a_hz[2], a_hn[2];
        #pragma unroll
        for (int c = 0; c < 2; c++) {
            a_ir[c] = 0ull; a_iz[c] = 0ull; a_in[c] = 0ull;
            a_hr[c] = 0ull; a_hz[c] = 0ull; a_hn[c] = 0ull;
        }

        #pragma unroll
        for (int c = 0; c < 2; c++) {
            const ulonglong2* wr = (const ulonglong2*)(s_wih + (size_t)(ob + c) * 64);
            const ulonglong2* wz = (const ulonglong2*)(s_wih + (size_t)(32 + ob + c) * 64);
            const ulonglong2* wn = (const ulonglong2*)(s_wih + (size_t)(64 + ob + c) * 64);
            const ulonglong2* vr = (const ulonglong2*)(s_whh + (size_t)(ob + c) * 32);
            const ulonglong2* vz = (const ulonglong2*)(s_whh + (size_t)(32 + ob + c) * 32);
            const ulonglong2* vn = (const ulonglong2*)(s_whh + (size_t)(64 + ob + c) * 32);

            #pragma unroll
            for (int p = 0; p < 8; p++) {
                ulonglong2 w;
                // W_ih x-half
                w = wr[p];
                a_ir[c] = fma2(w.x, xp[2*p], a_ir[c]);
                a_ir[c] = fma2(w.y, xp[2*p+1], a_ir[c]);
                w = wz[p];
                a_iz[c] = fma2(w.x, xp[2*p], a_iz[c]);
                a_iz[c] = fma2(w.y, xp[2*p+1], a_iz[c]);
                w = wn[p];
                a_in[c] = fma2(w.x, xp[2*p], a_in[c]);
                a_in[c] = fma2(w.y, xp[2*p+1], a_in[c]);
                // W_ih m-half
                w = wr[8 + p];
                a_ir[c] = fma2(w.x, mp[2*p], a_ir[c]);
                a_ir[c] = fma2(w.y, mp[2*p+1], a_ir[c]);
                w = wz[8 + p];
                a_iz[c] = fma2(w.x, mp[2*p], a_iz[c]);
                a_iz[c] = fma2(w.y, mp[2*p+1], a_iz[c]);
                w = wn[8 + p];
                a_in[c] = fma2(w.x, mp[2*p], a_in[c]);
                a_in[c] = fma2(w.y, mp[2*p+1], a_in[c]);
                // W_hh (x only)
                w = vr[p];
                a_hr[c] = fma2(w.x, xp[2*p], a_hr[c]);
                a_hr[c] = fma2(w.y, xp[2*p+1], a_hr[c]);
                w = vz[p];
                a_hz[c] = fma2(w.x, xp[2*p], a_hz[c]);
                a_hz[c] = fma2(w.y, xp[2*p+1], a_hz[c]);
                w = vn[p];
                a_hn[c] = fma2(w.x, xp[2*p], a_hn[c]);
                a_hn[c] = fma2(w.y, xp[2*p+1], a_hn[c]);
            }
        }

        const float2 xv = unpack2(xp[ob >> 1]);   // x[ob], x[ob+1]
        float outv[2];
        #pragma unroll
        for (int c = 0; c < 2; c++) {
            const float2 fir = unpack2(a_ir[c]);
            const float2 fiz = unpack2(a_iz[c]);
            const float2 fin = unpack2(a_in[c]);
            const float2 fhr = unpack2(a_hr[c]);
            const float2 fhz = unpack2(a_hz[c]);
            const float2 fhn = unpack2(a_hn[c]);
            const float ir = fir.x + fir.y + s_bih[ob + c];
            const float iz = fiz.x + fiz.y + s_bih[32 + ob + c];
            const float in_ = fin.x + fin.y + s_bih[64 + ob + c];
            const float hr = fhr.x + fhr.y + s_bhh[ob + c];
            const float hz = fhz.x + fhz.y + s_bhh[32 + ob + c];
            const float hn = fhn.x + fhn.y + s_bhh[64 + ob + c];
            const float r = sigmoidf_(ir + hr);
            const float z = sigmoidf_(iz + hz);
            const float nn2 = tanhf(in_ + r * hn);
            const float hp = (c == 0) ? xv.x : xv.y;
            outv[c] = (1.f - z) * nn2 + z * hp;
        }
        if (valid) {
            *(float2*)(xo + (size_t)n * HDIM + ob) = make_float2(outv[0], outv[1]);
        }
    }
}

// ============================================================
// launch
// ============================================================
extern "C" void kernel_launch(void* const* d_in, const int* in_sizes, int n_in,
                              void* d_out, int out_size) {
    const float* x     = (const float*)d_in[0];
    const float* ed    = (const float*)d_in[1];
    const int*   edges = (const int*)d_in[2];
    const int wb = n_in - 8;   // weights are the last 8 inputs
    const float* W1   = (const float*)d_in[wb + 0];
    const float* b1   = (const float*)d_in[wb + 1];
    const float* W2   = (const float*)d_in[wb + 2];
    const float* b2   = (const float*)d_in[wb + 3];
    const float* W_ih = (const float*)d_in[wb + 4];
    const float* W_hh = (const float*)d_in[wb + 5];
    const float* b_ih = (const float*)d_in[wb + 6];
    const float* b_hh = (const float*)d_in[wb + 7];
    float* out = (float*)d_out;

    const int n4 = N_NODES * HDIM / 4;
    const int g4 = (n4 + 255) / 256;

    copy_x_kernel<<<g4, 256>>>(x);
    edge_mlp_kernel<<<N_EDGES / 64, 256>>>(ed, W1, b1, W2, b2);

    const int msg_grid = N_EDGES / 8;                   // warp per edge
    const int gru_grid = (2 * N_NODES + 127) / 128;     // 2 threads per node

    for (int t = 0; t < T_ITERS; t++) {
        msg_kernel<<<msg_grid, 256>>>(edges, t);
        gru_kernel<<<gru_grid, 128>>>(W_ih, W_hh, b_ih, b_hh, out, t);
    }
}

// round 7
// speedup vs baseline: 1.0716x; 1.0716x over previous
#include <cuda_runtime.h>

#define N_NODES 50000
#define N_EDGES 200000
#define HDIM 32
#define T_ITERS 8

// ---------------- scratch (device globals: no allocation allowed) ----------
__device__ float g_A[(size_t)N_EDGES * 1024];   // A per edge, fp32, layout [e][j][i]
__device__ float g_m[N_NODES * HDIM];           // aggregated messages
__device__ float g_x0[N_NODES * HDIM];          // ping
__device__ float g_x1[N_NODES * HDIM];          // pong

// ---------------- packed f32x2 helpers (sm_100+) ----------------
__device__ __forceinline__ unsigned long long fma2(unsigned long long a,
                                                   unsigned long long b,
                                                   unsigned long long c) {
    unsigned long long d;
    asm("fma.rn.f32x2 %0, %1, %2, %3;" : "=l"(d) : "l"(a), "l"(b), "l"(c));
    return d;
}
__device__ __forceinline__ unsigned long long pack2(float x, float y) {
    unsigned long long d;
    asm("mov.b64 %0, {%1, %2};" : "=l"(d) : "f"(x), "f"(y));
    return d;
}
__device__ __forceinline__ float2 unpack2(unsigned long long v) {
    float2 r;
    asm("mov.b64 {%0, %1}, %2;" : "=f"(r.x), "=f"(r.y) : "l"(v));
    return r;
}
__device__ __forceinline__ float sigmoidf_(float v) {
    return 1.0f / (1.0f + __expf(-v));
}

// ============================================================
// copy input x -> g_x0, zero g_m
// ============================================================
__global__ void copy_x_kernel(const float* __restrict__ x) {
    int i = blockIdx.x * blockDim.x + threadIdx.x;
    if (i < N_NODES * HDIM / 4) {
        ((float4*)g_x0)[i] = ((const float4*)x)[i];
        ((float4*)g_m)[i]  = make_float4(0.f, 0.f, 0.f, 0.f);
    }
}

// ============================================================
// Edge MLP (unchanged — proven):
//   hid = relu(edge_data @ W1^T + b1)            [E,64]
//   A   = relu(hid @ W2^T + b2)                  [E,1024], fp32, stored [e][j][i]
// ============================================================
__global__ __launch_bounds__(256, 2) void edge_mlp_kernel(
    const float* __restrict__ ed, const float* __restrict__ W1,
    const float* __restrict__ b1, const float* __restrict__ W2,
    const float* __restrict__ b2)
{
    __shared__ float s_h2[64 * 132];  // [k][2e]
    __shared__ float s_w[64 * 128];   // [k][swizzled q]

    const int tid = threadIdx.x;
    const size_t e0 = (size_t)blockIdx.x * 64;

    {
        const int o  = tid & 63;
        const int eg = (tid >> 6) * 16;
        float w[16];
        #pragma unroll
        for (int q = 0; q < 4; q++) {
            float4 v = __ldg((const float4*)(W1 + o * 16) + q);
            w[4*q+0] = v.x; w[4*q+1] = v.y; w[4*q+2] = v.z; w[4*q+3] = v.w;
        }
        const float bb = __ldg(b1 + o);
        #pragma unroll 4
        for (int ii = 0; ii < 16; ii++) {
            const int e = eg + ii;
            const float4* ep = (const float4*)(ed + (e0 + e) * 16);
            float acc = bb;
            #pragma unroll
            for (int q = 0; q < 4; q++) {
                float4 v = __ldg(ep + q);
                acc += v.x * w[4*q+0] + v.y * w[4*q+1]
                     + v.z * w[4*q+2] + v.w * w[4*q+3];
            }
            acc = fmaxf(acc, 0.f);
            s_h2[o * 132 + 2 * e + 0] = acc;
            s_h2[o * 132 + 2 * e + 1] = acc;
        }
    }
    __syncthreads();

    const int m  = tid & 15;
    const int ey = (tid >> 4) * 4;

    for (int qt = 0; qt < 8; qt++) {
        if (qt) __syncthreads();

        #pragma unroll
        for (int r = 0; r < 8; r++) {
            const int slot = tid + r * 256;
            const int q   = slot >> 4;
            const int k4  = slot & 15;
            const int qg  = qt * 128 + q;
            const int o   = ((qg & 31) << 5) | (qg >> 5);
            float4 v = __ldg((const float4*)(W2 + (size_t)o * 64) + k4);
            const int qlo = q & 3;
            const int qc  = q >> 2;
            #pragma unroll
            for (int c = 0; c < 4; c++) {
                const int k = 4 * k4 + c;
                const int p = qc ^ ((k >> 2) & 7);
                const float vv = (c == 0) ? v.x : (c == 1) ? v.y : (c == 2) ? v.z : v.w;
                s_w[k * 128 + 4 * p + qlo] = vv;
            }
        }
        __syncthreads();

        float bq[8];
        #pragma unroll
        for (int c = 0; c < 8; c++) {
            const int qg = qt * 128 + ((c < 4) ? (4 * m + c) : (64 + 4 * m + (c - 4)));
            const int o  = ((qg & 31) << 5) | (qg >> 5);
            bq[c] = __ldg(b2 + o);
        }
        unsigned long long acc[4][4];
        {
            const unsigned long long p0 = pack2(bq[0], bq[1]);
            const unsigned long long p1 = pack2(bq[2], bq[3]);
            const unsigned long long p2 = pack2(bq[4], bq[5]);
            const unsigned long long p3 = pack2(bq[6], bq[7]);
            #pragma unroll
            for (int je = 0; je < 4; je++) {
                acc[je][0] = p0; acc[je][1] = p1; acc[je][2] = p2; acc[je][3] = p3;
            }
        }

        #pragma unroll 8
        for (int k = 0; k < 64; k++) {
            const int s = (k >> 2) & 7;
            const float* wrow = s_w + k * 128;
            const ulonglong2 wA = *(const ulonglong2*)(wrow + 4 * (m ^ s));
            const ulonglong2 wB = *(const ulonglong2*)(wrow + 4 * ((m ^ s) + 16));
            const float* hrow = s_h2 + k * 132 + 2 * ey;
            const ulonglong2 hA = *(const ulonglong2*)(hrow);
            const ulonglong2 hB = *(const ulonglong2*)(hrow + 4);
            acc[0][0] = fma2(wA.x, hA.x, acc[0][0]);
            acc[0][1] = fma2(wA.y, hA.x, acc[0][1]);
            acc[0][2] = fma2(wB.x, hA.x, acc[0][2]);
            acc[0][3] = fma2(wB.y, hA.x, acc[0][3]);
            acc[1][0] = fma2(wA.x, hA.y, acc[1][0]);
            acc[1][1] = fma2(wA.y, hA.y, acc[1][1]);
            acc[1][2] = fma2(wB.x, hA.y, acc[1][2]);
            acc[1][3] = fma2(wB.y, hA.y, acc[1][3]);
            acc[2][0] = fma2(wA.x, hB.x, acc[2][0]);
            acc[2][1] = fma2(wA.y, hB.x, acc[2][1]);
            acc[2][2] = fma2(wB.x, hB.x, acc[2][2]);
            acc[2][3] = fma2(wB.y, hB.x, acc[2][3]);
            acc[3][0] = fma2(wA.x, hB.y, acc[3][0]);
            acc[3][1] = fma2(wA.y, hB.y, acc[3][1]);
            acc[3][2] = fma2(wB.x, hB.y, acc[3][2]);
            acc[3][3] = fma2(wB.y, hB.y, acc[3][3]);
        }

        #pragma unroll
        for (int je = 0; je < 4; je++) {
            float* base = g_A + (e0 + ey + je) * 1024 + qt * 128;
            const float2 a0 = unpack2(acc[je][0]);
            const float2 a1 = unpack2(acc[je][1]);
            const float2 a2 = unpack2(acc[je][2]);
            const float2 a3 = unpack2(acc[je][3]);
            *(float4*)(base + 4 * m) =
                make_float4(fmaxf(a0.x, 0.f), fmaxf(a0.y, 0.f),
                            fmaxf(a1.x, 0.f), fmaxf(a1.y, 0.f));
            *(float4*)(base + 64 + 4 * m) =
                make_float4(fmaxf(a2.x, 0.f), fmaxf(a2.y, 0.f),
                            fmaxf(a3.x, 0.f), fmaxf(a3.y, 0.f));
        }
    }
}

// ============================================================
// Message pass: warp per edge. A read with streaming hint (zero reuse).
// ============================================================
__global__ __launch_bounds__(256) void msg_kernel(const int* __restrict__ edges, int t) {
    const float* __restrict__ xc = (t & 1) ? g_x1 : g_x0;

    const int warp = (blockIdx.x * blockDim.x + threadIdx.x) >> 5;
    const int lane = threadIdx.x & 31;
    if (warp >= N_EDGES) return;

    const int src = __ldg(edges + 2 * warp);
    const int dst = __ldg(edges + 2 * warp + 1);

    const float xv = __ldg(xc + (size_t)src * HDIM + lane);
    const float* Ap = g_A + (size_t)warp * 1024 + lane;

    float acc = 0.f;
    #pragma unroll
    for (int j = 0; j < 32; j++) {
        const float a  = __ldcs(Ap + j * 32);   // streaming: evict-first
        const float xj = __shfl_sync(0xffffffffu, xv, j);
        acc = fmaf(a, xj, acc);
    }

    atomicAdd(g_m + (size_t)src * HDIM + lane, acc);
    if (src != dst) atomicAdd(g_m + (size_t)dst * HDIM + lane, acc);
}

// ============================================================
// GRU as block-GEMM (edge_mlp phase-2 machinery):
//   block = 64 nodes, 256 threads.
//   u[k] = [x(0..31); m(32..63)] staged as duplicated pairs, k-major.
//   Phase A: gi[q=128pad][64n], k=64, W_ih rows (q>=96 zero).
//   Phase B: gh[q=128pad][64n], k=32 (x), W_hh rows.
//   q<32: r-gate hid q; 32..63: z hid q-32; 64..95: n hid q-64.
//   Thread m<8 owns r & n pre-acts for hid 4m..4m+3; z comes from
//   lane m+8 (same warp) via shfl_xor(8). Also zeroes g_m.
// ============================================================
__global__ __launch_bounds__(256, 2) void gru_kernel(
    const float* __restrict__ W_ih, const float* __restrict__ W_hh,
    const float* __restrict__ b_ih, const float* __restrict__ b_hh,
    float* __restrict__ dout, int t)
{
    __shared__ float s_u2[64 * 132];  // [k][2n] duplicated pairs
    __shared__ float s_w[64 * 128];   // [k][swizzled q]

    const float* __restrict__ xc = (t & 1) ? g_x1 : g_x0;
    float* __restrict__ xo = (t == T_ITERS - 1) ? dout : ((t & 1) ? g_x0 : g_x1);

    const int tid = threadIdx.x;
    const int n0 = blockIdx.x * 64;

    // ---- stage u = [x; m] as dup pairs; zero g_m after reading ----
    for (int idx = tid; idx < 64 * 16; idx += 256) {
        const int node = idx >> 4;       // 0..63
        const int q4   = idx & 15;       // 0..15 (8 x-chunks, 8 m-chunks)
        int gn = n0 + node;
        const bool v_ = (gn < N_NODES);
        if (!v_) gn = N_NODES - 1;
        float4 v;
        int kbase;
        if (q4 < 8) {
            v = __ldg((const float4*)(xc + (size_t)gn * HDIM) + q4);
            kbase = 4 * q4;
        } else {
            float4* mq = (float4*)(g_m + (size_t)gn * HDIM) + (q4 - 8);
            v = *mq;
            if (v_) *mq = make_float4(0.f, 0.f, 0.f, 0.f);
            kbase = 32 + 4 * (q4 - 8);
        }
        #pragma unroll
        for (int c = 0; c < 4; c++) {
            const float vv = (c == 0) ? v.x : (c == 1) ? v.y : (c == 2) ? v.z : v.w;
            s_u2[(kbase + c) * 132 + 2 * node + 0] = vv;
            s_u2[(kbase + c) * 132 + 2 * node + 1] = vv;
        }
    }

    const int m  = tid & 15;
    const int ey = (tid >> 4) * 4;

    // ---- stage W_ih k-major swizzled (q>=96 -> 0) ----
    #pragma unroll
    for (int r = 0; r < 8; r++) {
        const int slot = tid + r * 256;   // 2048 slots: q(128) x k4(16)
        const int q  = slot >> 4;
        const int k4 = slot & 15;
        float4 v = make_float4(0.f, 0.f, 0.f, 0.f);
        if (q < 96) v = __ldg((const float4*)(W_ih + (size_t)q * 64) + k4);
        const int qlo = q & 3;
        const int qc  = q >> 2;
        #pragma unroll
        for (int c = 0; c < 4; c++) {
            const int k = 4 * k4 + c;
            const int p = qc ^ ((k >> 2) & 7);
            const float vv = (c == 0) ? v.x : (c == 1) ? v.y : (c == 2) ? v.z : v.w;
            s_w[k * 128 + 4 * p + qlo] = vv;
        }
    }
    __syncthreads();

    // ---- bias init (phase A: b_ih) ----
    unsigned long long accA[4][4];
    {
        float bq[8];
        #pragma unroll
        for (int c = 0; c < 8; c++) {
            const int q = (c < 4) ? (4 * m + c) : (64 + 4 * m + (c - 4));
            bq[c] = (q < 96) ? __ldg(b_ih + q) : 0.f;
        }
        const unsigned long long p0 = pack2(bq[0], bq[1]);
        const unsigned long long p1 = pack2(bq[2], bq[3]);
        const unsigned long long p2 = pack2(bq[4], bq[5]);
        const unsigned long long p3 = pack2(bq[6], bq[7]);
        #pragma unroll
        for (int je = 0; je < 4; je++) {
            accA[je][0] = p0; accA[je][1] = p1; accA[je][2] = p2; accA[je][3] = p3;
        }
    }

    // ---- phase A: k = 0..63 over u ----
    #pragma unroll 8
    for (int k = 0; k < 64; k++) {
        const int s = (k >> 2) & 7;
        const float* wrow = s_w + k * 128;
        const ulonglong2 wA = *(const ulonglong2*)(wrow + 4 * (m ^ s));
        const ulonglong2 wB = *(const ulonglong2*)(wrow + 4 * ((m ^ s) + 16));
        const float* urow = s_u2 + k * 132 + 2 * ey;
        const ulonglong2 uA = *(const ulonglong2*)(urow);
        const ulonglong2 uB = *(const ulonglong2*)(urow + 4);
        accA[0][0] = fma2(wA.x, uA.x, accA[0][0]);
        accA[0][1] = fma2(wA.y, uA.x, accA[0][1]);
        accA[0][2] = fma2(wB.x, uA.x, accA[0][2]);
        accA[0][3] = fma2(wB.y, uA.x, accA[0][3]);
        accA[1][0] = fma2(wA.x, uA.y, accA[1][0]);
        accA[1][1] = fma2(wA.y, uA.y, accA[1][1]);
        accA[1][2] = fma2(wB.x, uA.y, accA[1][2]);
        accA[1][3] = fma2(wB.y, uA.y, accA[1][3]);
        accA[2][0] = fma2(wA.x, uB.x, accA[2][0]);
        accA[2][1] = fma2(wA.y, uB.x, accA[2][1]);
        accA[2][2] = fma2(wB.x, uB.x, accA[2][2]);
        accA[2][3] = fma2(wB.y, uB.x, accA[2][3]);
        accA[3][0] = fma2(wA.x, uB.y, accA[3][0]);
        accA[3][1] = fma2(wA.y, uB.y, accA[3][1]);
        accA[3][2] = fma2(wB.x, uB.y, accA[3][2]);
        accA[3][3] = fma2(wB.y, uB.y, accA[3][3]);
    }
    __syncthreads();   // accA in regs; s_w free for W_hh

    // ---- stage W_hh k-major swizzled (k=32) ----
    #pragma unroll
    for (int r = 0; r < 4; r++) {
        const int slot = tid + r * 256;   // 1024 slots: q(128) x k4(8)
        const int q  = slot >> 3;
        const int k4 = slot & 7;
        float4 v = make_float4(0.f, 0.f, 0.f, 0.f);
        if (q < 96) v = __ldg((const float4*)(W_hh + (size_t)q * 32) + k4);
        const int qlo = q & 3;
        const int qc  = q >> 2;
        #pragma unroll
        for (int c = 0; c < 4; c++) {
            const int k = 4 * k4 + c;
            const int p = qc ^ ((k >> 2) & 7);
            const float vv = (c == 0) ? v.x : (c == 1) ? v.y : (c == 2) ? v.z : v.w;
            s_w[k * 128 + 4 * p + qlo] = vv;
        }
    }
    __syncthreads();

    // ---- bias init (phase B: b_hh) ----
    unsigned long long accB[4][4];
    {
        float bq[8];
        #pragma unroll
        for (int c = 0; c < 8; c++) {
            const int q = (c < 4) ? (4 * m + c) : (64 + 4 * m + (c - 4));
            bq[c] = (q < 96) ? __ldg(b_hh + q) : 0.f;
        }
        const unsigned long long p0 = pack2(bq[0], bq[1]);
        const unsigned long long p1 = pack2(bq[2], bq[3]);
        const unsigned long long p2 = pack2(bq[4], bq[5]);
        const unsigned long long p3 = pack2(bq[6], bq[7]);
        #pragma unroll
        for (int je = 0; je < 4; je++) {
            accB[je][0] = p0; accB[je][1] = p1; accB[je][2] = p2; accB[je][3] = p3;
        }
    }

    // ---- phase B: k = 0..31 over x part of u ----
    #pragma unroll 8
    for (int k = 0; k < 32; k++) {
        const int s = (k >> 2) & 7;
        const float* wrow = s_w + k * 128;
        const ulonglong2 wA = *(const ulonglong2*)(wrow + 4 * (m ^ s));
        const ulonglong2 wB = *(const ulonglong2*)(wrow + 4 * ((m ^ s) + 16));
        const float* urow = s_u2 + k * 132 + 2 * ey;
        const ulonglong2 uA = *(const ulonglong2*)(urow);
        const ulonglong2 uB = *(const ulonglong2*)(urow + 4);
        accB[0][0] = fma2(wA.x, uA.x, accB[0][0]);
        accB[0][1] = fma2(wA.y, uA.x, accB[0][1]);
        accB[0][2] = fma2(wB.x, uA.x, accB[0][2]);
        accB[0][3] = fma2(wB.y, uA.x, accB[0][3]);
        accB[1][0] = fma2(wA.x, uA.y, accB[1][0]);
        accB[1][1] = fma2(wA.y, uA.y, accB[1][1]);
        accB[1][2] = fma2(wB.x, uA.y, accB[1][2]);
        accB[1][3] = fma2(wB.y, uA.y, accB[1][3]);
        accB[2][0] = fma2(wA.x, uB.x, accB[2][0]);
        accB[2][1] = fma2(wA.y, uB.x, accB[2][1]);
        accB[2][2] = fma2(wB.x, uB.x, accB[2][2]);
        accB[2][3] = fma2(wB.y, uB.x, accB[2][3]);
        accB[3][0] = fma2(wA.x, uB.y, accB[3][0]);
        accB[3][1] = fma2(wA.y, uB.y, accB[3][1]);
        accB[3][2] = fma2(wB.x, uB.y, accB[3][2]);
        accB[3][3] = fma2(wB.y, uB.y, accB[3][3]);
    }

    // ---- epilogue ----
    // All lanes: z-sums for their chunk-m (q=4m..4m+3): gi + gh, per node.
    // shfl_xor(8): lane m<8 receives z pre-acts (hid 4m..4m+3) from lane m+8.
    #pragma unroll
    for (int je = 0; je < 4; je++) {
        const float2 s0 = unpack2(accA[je][0]);
        const float2 t0 = unpack2(accB[je][0]);
        const float2 s1 = unpack2(accA[je][1]);
        const float2 t1 = unpack2(accB[je][1]);
        float zsum[4] = { s0.x + t0.x, s0.y + t0.y, s1.x + t1.x, s1.y + t1.y };
        float zr[4];
        #pragma unroll
        for (int c = 0; c < 4; c++)
            zr[c] = __shfl_xor_sync(0xffffffffu, zsum[c], 8);

        if (m < 8) {
            const int node = n0 + ey + je;
            // r pre-acts (chunk m): accA/accB [je][0..1]
            // n pre-acts (chunk m+16, q=64+4m..): accA/accB [je][2..3]
            const float2 in0 = unpack2(accA[je][2]);
            const float2 in1 = unpack2(accA[je][3]);
            const float2 hn0 = unpack2(accB[je][2]);
            const float2 hn1 = unpack2(accB[je][3]);
            const float i_n[4] = { in0.x, in0.y, in1.x, in1.y };
            const float h_n[4] = { hn0.x, hn0.y, hn1.x, hn1.y };
            const float r_s[4] = { s0.x + t0.x, s0.y + t0.y, s1.x + t1.x, s1.y + t1.y };

            float outv[4];
            #pragma unroll
            for (int c = 0; c < 4; c++) {
                const float r = sigmoidf_(r_s[c]);
                const float z = sigmoidf_(zr[c]);
                const float nn2 = tanhf(i_n[c] + r * h_n[c]);
                const float hp = s_u2[(4 * m + c) * 132 + 2 * (ey + je)];
                outv[c] = (1.f - z) * nn2 + z * hp;
            }
            if (node < N_NODES) {
                *(float4*)(xo + (size_t)node * HDIM + 4 * m) =
                    make_float4(outv[0], outv[1], outv[2], outv[3]);
            }
        }
    }
}

// ============================================================
// launch
// ============================================================
extern "C" void kernel_launch(void* const* d_in, const int* in_sizes, int n_in,
                              void* d_out, int out_size) {
    const float* x     = (const float*)d_in[0];
    const float* ed    = (const float*)d_in[1];
    const int*   edges = (const int*)d_in[2];
    const int wb = n_in - 8;   // weights are the last 8 inputs
    const float* W1   = (const float*)d_in[wb + 0];
    const float* b1   = (const float*)d_in[wb + 1];
    const float* W2   = (const float*)d_in[wb + 2];
    const float* b2   = (const float*)d_in[wb + 3];
    const float* W_ih = (const float*)d_in[wb + 4];
    const float* W_hh = (const float*)d_in[wb + 5];
    const float* b_ih = (const float*)d_in[wb + 6];
    const float* b_hh = (const float*)d_in[wb + 7];
    float* out = (float*)d_out;

    const int n4 = N_NODES * HDIM / 4;
    const int g4 = (n4 + 255) / 256;

    copy_x_kernel<<<g4, 256>>>(x);
    edge_mlp_kernel<<<N_EDGES / 64, 256>>>(ed, W1, b1, W2, b2);

    const int msg_grid = N_EDGES / 8;                 // warp per edge
    const int gru_grid = (N_NODES + 63) / 64;         // 64 nodes per block

    for (int t = 0; t < T_ITERS; t++) {
        msg_kernel<<<msg_grid, 256>>>(edges, t);
        gru_kernel<<<gru_grid, 256>>>(W_ih, W_hh, b_ih, b_hh, out, t);
    }
}

// round 8
// speedup vs baseline: 1.1547x; 1.0776x over previous
#include <cuda_runtime.h>
#include <cuda_fp16.h>

#define N_NODES 50000
#define N_EDGES 200000
#define HDIM 32
#define T_ITERS 8

// ---------------- scratch (device globals: no allocation allowed) ----------
// A stored as 3 bytes/element: fp16 hi + int8 mantissa extension (ulp/256 scale)
// layout [e][i][j]: lane i reads its row of 32 contiguous elements.
__device__ __half       g_Ah[(size_t)N_EDGES * 1024];  // 409.6 MB
__device__ signed char  g_Al[(size_t)N_EDGES * 1024];  // 204.8 MB
__device__ float g_m[N_NODES * HDIM];
__device__ float g_x0[N_NODES * HDIM];
__device__ float g_x1[N_NODES * HDIM];

// ---------------- packed f32x2 helpers (sm_100+) ----------------
__device__ __forceinline__ unsigned long long fma2(unsigned long long a,
                                                   unsigned long long b,
                                                   unsigned long long c) {
    unsigned long long d;
    asm("fma.rn.f32x2 %0, %1, %2, %3;" : "=l"(d) : "l"(a), "l"(b), "l"(c));
    return d;
}
__device__ __forceinline__ unsigned long long pack2(float x, float y) {
    unsigned long long d;
    asm("mov.b64 %0, {%1, %2};" : "=l"(d) : "f"(x), "f"(y));
    return d;
}
__device__ __forceinline__ float2 unpack2(unsigned long long v) {
    float2 r;
    asm("mov.b64 {%0, %1}, %2;" : "=f"(r.x), "=f"(r.y) : "l"(v));
    return r;
}
__device__ __forceinline__ float sigmoidf_(float v) {
    return 1.0f / (1.0f + __expf(-v));
}

// encode 4 relu'd floats -> 4 fp16 (uint2) + 4 int8 (uint)
__device__ __forceinline__ void enc4(float a0, float a1, float a2, float a3,
                                     uint2& hp, unsigned& qp) {
    float av[4] = {a0, a1, a2, a3};
    unsigned hs[4]; int qs[4];
    #pragma unroll
    for (int c = 0; c < 4; c++) {
        const float a = fmaxf(av[c], 0.f);
        const __half hh = __float2half_rn(a);
        const unsigned hb = (unsigned)__half_as_ushort(hh);
        const float hf = __half2float(hh);
        const int e5 = (hb >> 10) & 31;
        const float si = __uint_as_float((unsigned)(160 - e5) << 23); // 2^(33-e5)
        int qi = __float2int_rn((a - hf) * si);
        qi = max(-127, min(127, qi));
        hs[c] = hb; qs[c] = qi;
    }
    hp.x = hs[0] | (hs[1] << 16);
    hp.y = hs[2] | (hs[3] << 16);
    qp = (qs[0] & 0xFF) | ((qs[1] & 0xFF) << 8)
       | ((qs[2] & 0xFF) << 16) | ((qs[3] & 0xFF) << 24);
}

// ============================================================
// copy input x -> g_x0, zero g_m
// ============================================================
__global__ void copy_x_kernel(const float* __restrict__ x) {
    int i = blockIdx.x * blockDim.x + threadIdx.x;
    if (i < N_NODES * HDIM / 4) {
        ((float4*)g_x0)[i] = ((const float4*)x)[i];
        ((float4*)g_m)[i]  = make_float4(0.f, 0.f, 0.f, 0.f);
    }
}

// ============================================================
// Edge MLP:
//   hid = relu(edge_data @ W1^T + b1)   [E,64]
//   A   = relu(hid @ W2^T + b2)         [E,1024] encoded 3B, layout [e][o], o=i*32+j
// Natural o-ordering (no permutation needed with the [e][i][j] layout).
// ============================================================
__global__ __launch_bounds__(256, 2) void edge_mlp_kernel(
    const float* __restrict__ ed, const float* __restrict__ W1,
    const float* __restrict__ b1, const float* __restrict__ W2,
    const float* __restrict__ b2)
{
    __shared__ float s_h2[64 * 132];  // [k][2e] duplicated pairs
    __shared__ float s_w[64 * 128];   // [k][swizzled q]

    const int tid = threadIdx.x;
    const size_t e0 = (size_t)blockIdx.x * 64;

    // ---------- phase 1: hid ----------
    {
        const int o  = tid & 63;
        const int eg = (tid >> 6) * 16;
        float w[16];
        #pragma unroll
        for (int q = 0; q < 4; q++) {
            float4 v = __ldg((const float4*)(W1 + o * 16) + q);
            w[4*q+0] = v.x; w[4*q+1] = v.y; w[4*q+2] = v.z; w[4*q+3] = v.w;
        }
        const float bb = __ldg(b1 + o);
        #pragma unroll 4
        for (int ii = 0; ii < 16; ii++) {
            const int e = eg + ii;
            const float4* ep = (const float4*)(ed + (e0 + e) * 16);
            float acc = bb;
            #pragma unroll
            for (int q = 0; q < 4; q++) {
                float4 v = __ldg(ep + q);
                acc += v.x * w[4*q+0] + v.y * w[4*q+1]
                     + v.z * w[4*q+2] + v.w * w[4*q+3];
            }
            acc = fmaxf(acc, 0.f);
            s_h2[o * 132 + 2 * e + 0] = acc;
            s_h2[o * 132 + 2 * e + 1] = acc;
        }
    }
    __syncthreads();

    const int m  = tid & 15;
    const int ey = (tid >> 4) * 4;

    for (int qt = 0; qt < 8; qt++) {
        if (qt) __syncthreads();

        // ---- stage W2 tile k-major, XOR-swizzled; q maps to o directly ----
        #pragma unroll
        for (int r = 0; r < 8; r++) {
            const int slot = tid + r * 256;
            const int q   = slot >> 4;
            const int k4  = slot & 15;
            const int o   = qt * 128 + q;
            float4 v = __ldg((const float4*)(W2 + (size_t)o * 64) + k4);
            const int qlo = q & 3;
            const int qc  = q >> 2;
            #pragma unroll
            for (int c = 0; c < 4; c++) {
                const int k = 4 * k4 + c;
                const int p = qc ^ ((k >> 2) & 7);
                const float vv = (c == 0) ? v.x : (c == 1) ? v.y : (c == 2) ? v.z : v.w;
                s_w[k * 128 + 4 * p + qlo] = vv;
            }
        }
        __syncthreads();

        float bq[8];
        #pragma unroll
        for (int c = 0; c < 8; c++) {
            const int o = qt * 128 + ((c < 4) ? (4 * m + c) : (64 + 4 * m + (c - 4)));
            bq[c] = __ldg(b2 + o);
        }
        unsigned long long acc[4][4];
        {
            const unsigned long long p0 = pack2(bq[0], bq[1]);
            const unsigned long long p1 = pack2(bq[2], bq[3]);
            const unsigned long long p2 = pack2(bq[4], bq[5]);
            const unsigned long long p3 = pack2(bq[6], bq[7]);
            #pragma unroll
            for (int je = 0; je < 4; je++) {
                acc[je][0] = p0; acc[je][1] = p1; acc[je][2] = p2; acc[je][3] = p3;
            }
        }

        #pragma unroll 8
        for (int k = 0; k < 64; k++) {
            const int s = (k >> 2) & 7;
            const float* wrow = s_w + k * 128;
            const ulonglong2 wA = *(const ulonglong2*)(wrow + 4 * (m ^ s));
            const ulonglong2 wB = *(const ulonglong2*)(wrow + 4 * ((m ^ s) + 16));
            const float* hrow = s_h2 + k * 132 + 2 * ey;
            const ulonglong2 hA = *(const ulonglong2*)(hrow);
            const ulonglong2 hB = *(const ulonglong2*)(hrow + 4);
            acc[0][0] = fma2(wA.x, hA.x, acc[0][0]);
            acc[0][1] = fma2(wA.y, hA.x, acc[0][1]);
            acc[0][2] = fma2(wB.x, hA.x, acc[0][2]);
            acc[0][3] = fma2(wB.y, hA.x, acc[0][3]);
            acc[1][0] = fma2(wA.x, hA.y, acc[1][0]);
            acc[1][1] = fma2(wA.y, hA.y, acc[1][1]);
            acc[1][2] = fma2(wB.x, hA.y, acc[1][2]);
            acc[1][3] = fma2(wB.y, hA.y, acc[1][3]);
            acc[2][0] = fma2(wA.x, hB.x, acc[2][0]);
            acc[2][1] = fma2(wA.y, hB.x, acc[2][1]);
            acc[2][2] = fma2(wB.x, hB.x, acc[2][2]);
            acc[2][3] = fma2(wB.y, hB.x, acc[2][3]);
            acc[3][0] = fma2(wA.x, hB.y, acc[3][0]);
            acc[3][1] = fma2(wA.y, hB.y, acc[3][1]);
            acc[3][2] = fma2(wB.x, hB.y, acc[3][2]);
            acc[3][3] = fma2(wB.y, hB.y, acc[3][3]);
        }

        // ---- relu + 3-byte encode + coalesced stores ----
        #pragma unroll
        for (int je = 0; je < 4; je++) {
            const size_t ebase = (e0 + ey + je) * 1024 + qt * 128;
            const float2 a0 = unpack2(acc[je][0]);
            const float2 a1 = unpack2(acc[je][1]);
            const float2 a2 = unpack2(acc[je][2]);
            const float2 a3 = unpack2(acc[je][3]);
            uint2 hpA, hpB; unsigned qpA, qpB;
            enc4(a0.x, a0.y, a1.x, a1.y, hpA, qpA);
            enc4(a2.x, a2.y, a3.x, a3.y, hpB, qpB);
            *(uint2*)(g_Ah + ebase + 4 * m)        = hpA;
            *(uint2*)(g_Ah + ebase + 64 + 4 * m)   = hpB;
            *(unsigned*)(g_Al + ebase + 4 * m)      = qpA;
            *(unsigned*)(g_Al + ebase + 64 + 4 * m) = qpB;
        }
    }
}

// ============================================================
// Message pass: warp per edge, lane i owns row i (layout [e][i][j]).
// Front-batched vector loads (4x LDG.128 halves + 2x LDG.128 int8),
// decode a = hi + q * 2^(e5-33), dot with shfl-broadcast x.
// ============================================================
__global__ __launch_bounds__(256) void msg_kernel(const int* __restrict__ edges, int t) {
    const float* __restrict__ xc = (t & 1) ? g_x1 : g_x0;

    const int warp = (blockIdx.x * blockDim.x + threadIdx.x) >> 5;
    const int lane = threadIdx.x & 31;
    if (warp >= N_EDGES) return;

    const int src = __ldg(edges + 2 * warp);
    const int dst = __ldg(edges + 2 * warp + 1);

    const float xv = __ldg(xc + (size_t)src * HDIM + lane);

    const size_t rbase = (size_t)warp * 1024 + (size_t)lane * 32;
    const uint4* Hp = (const uint4*)(g_Ah + rbase);   // 32 halves = 4 x 16B
    const uint4* Qp = (const uint4*)(g_Al + rbase);   // 32 bytes  = 2 x 16B

    uint4 hv[4], qv[2];
    #pragma unroll
    for (int i = 0; i < 4; i++) hv[i] = __ldcs(Hp + i);
    #pragma unroll
    for (int i = 0; i < 2; i++) qv[i] = __ldcs(Qp + i);

    unsigned hw[16], qw[8];
    #pragma unroll
    for (int i = 0; i < 4; i++) {
        hw[4*i+0] = hv[i].x; hw[4*i+1] = hv[i].y;
        hw[4*i+2] = hv[i].z; hw[4*i+3] = hv[i].w;
    }
    #pragma unroll
    for (int i = 0; i < 2; i++) {
        qw[4*i+0] = qv[i].x; qw[4*i+1] = qv[i].y;
        qw[4*i+2] = qv[i].z; qw[4*i+3] = qv[i].w;
    }

    float acc = 0.f;
    #pragma unroll
    for (int u = 0; u < 16; u++) {
        const unsigned w = hw[u];
        const float f0 = __half2float(__ushort_as_half((unsigned short)(w & 0xFFFF)));
        const float f1 = __half2float(__ushort_as_half((unsigned short)(w >> 16)));
        const unsigned e0 = (w >> 10) & 31;
        const unsigned e1 = (w >> 26) & 31;
        const float s0 = __uint_as_float((e0 + 94) << 23);
        const float s1 = __uint_as_float((e1 + 94) << 23);
        const unsigned qb = qw[u >> 1];
        const int sh = (u & 1) * 16;
        const int q0 = (int)(signed char)(qb >> sh);
        const int q1 = (int)(signed char)(qb >> (sh + 8));
        const float a0 = fmaf((float)q0, s0, f0);
        const float a1 = fmaf((float)q1, s1, f1);
        const float x0 = __shfl_sync(0xffffffffu, xv, 2 * u);
        const float x1 = __shfl_sync(0xffffffffu, xv, 2 * u + 1);
        acc = fmaf(a0, x0, acc);
        acc = fmaf(a1, x1, acc);
    }

    atomicAdd(g_m + (size_t)src * HDIM + lane, acc);
    if (src != dst) atomicAdd(g_m + (size_t)dst * HDIM + lane, acc);
}

// ============================================================
// GRU cell (R5 version — proven 50.4us): 128-thread blocks, thread per
// node, packed f32x2 math, weights+biases in smem, zeroes g_m.
// ============================================================
__global__ __launch_bounds__(128, 4) void gru_kernel(
    const float* __restrict__ W_ih, const float* __restrict__ W_hh,
    const float* __restrict__ b_ih, const float* __restrict__ b_hh,
    float* __restrict__ dout, int t)
{
    __shared__ float s_wih[96 * 64];
    __shared__ float s_whh[96 * 32];
    __shared__ float s_bih[96];
    __shared__ float s_bhh[96];

    const float* __restrict__ xc = (t & 1) ? g_x1 : g_x0;
    float* __restrict__ xo = (t == T_ITERS - 1) ? dout : ((t & 1) ? g_x0 : g_x1);

    for (int idx = threadIdx.x; idx < 96 * 64 / 4; idx += 128)
        ((float4*)s_wih)[idx] = __ldg((const float4*)W_ih + idx);
    for (int idx = threadIdx.x; idx < 96 * 32 / 4; idx += 128)
        ((float4*)s_whh)[idx] = __ldg((const float4*)W_hh + idx);
    if (threadIdx.x < 96) {
        s_bih[threadIdx.x] = __ldg(b_ih + threadIdx.x);
        s_bhh[threadIdx.x] = __ldg(b_hh + threadIdx.x);
    }
    __syncthreads();

    const int n = blockIdx.x * 128 + threadIdx.x;
    const bool valid = (n < N_NODES);
    const int nn_ = valid ? n : (N_NODES - 1);

    unsigned long long xp[16], mp[16];
    {
        const float4* xq = (const float4*)(xc + (size_t)nn_ * HDIM);
        float4* mq = (float4*)(g_m + (size_t)nn_ * HDIM);
        #pragma unroll
        for (int i = 0; i < 8; i++) {
            float4 v = __ldg(xq + i);
            xp[2*i]   = pack2(v.x, v.y);
            xp[2*i+1] = pack2(v.z, v.w);
            float4 u = mq[i];
            mp[2*i]   = pack2(u.x, u.y);
            mp[2*i+1] = pack2(u.z, u.w);
        }
        if (valid) {
            #pragma unroll
            for (int i = 0; i < 8; i++) mq[i] = make_float4(0.f, 0.f, 0.f, 0.f);
        }
    }

    #pragma unroll 4
    for (int oc = 0; oc < 16; oc++) {
        const int ob = 2 * oc;
        unsigned long long a_ir[2], a_iz[2], a_in[2], a_hr[2], a_hz[2], a_hn[2];
        #pragma unroll
        for (int c = 0; c < 2; c++) {
            a_ir[c] = 0ull; a_iz[c] = 0ull; a_in[c] = 0ull;
            a_hr[c] = 0ull; a_hz[c] = 0ull; a_hn[c] = 0ull;
        }

        #pragma unroll
        for (int c = 0; c < 2; c++) {
            const ulonglong2* wr = (const ulonglong2*)(s_wih + (size_t)(ob + c) * 64);
            const ulonglong2* wz = (const ulonglong2*)(s_wih + (size_t)(32 + ob + c) * 64);
            const ulonglong2* wn = (const ulonglong2*)(s_wih + (size_t)(64 + ob + c) * 64);
            const ulonglong2* vr = (const ulonglong2*)(s_whh + (size_t)(ob + c) * 32);
            const ulonglong2* vz = (const ulonglong2*)(s_whh + (size_t)(32 + ob + c) * 32);
            const ulonglong2* vn = (const ulonglong2*)(s_whh + (size_t)(64 + ob + c) * 32);

            #pragma unroll
            for (int p = 0; p < 8; p++) {
                ulonglong2 w;
                w = wr[p];
                a_ir[c] = fma2(w.x, xp[2*p], a_ir[c]);
                a_ir[c] = fma2(w.y, xp[2*p+1], a_ir[c]);
                w = wz[p];
                a_iz[c] = fma2(w.x, xp[2*p], a_iz[c]);
                a_iz[c] = fma2(w.y, xp[2*p+1], a_iz[c]);
                w = wn[p];
                a_in[c] = fma2(w.x, xp[2*p], a_in[c]);
                a_in[c] = fma2(w.y, xp[2*p+1], a_in[c]);
                w = wr[8 + p];
                a_ir[c] = fma2(w.x, mp[2*p], a_ir[c]);
                a_ir[c] = fma2(w.y, mp[2*p+1], a_ir[c]);
                w = wz[8 + p];
                a_iz[c] = fma2(w.x, mp[2*p], a_iz[c]);
                a_iz[c] = fma2(w.y, mp[2*p+1], a_iz[c]);
                w = wn[8 + p];
                a_in[c] = fma2(w.x, mp[2*p], a_in[c]);
                a_in[c] = fma2(w.y, mp[2*p+1], a_in[c]);
                w = vr[p];
                a_hr[c] = fma2(w.x, xp[2*p], a_hr[c]);
                a_hr[c] = fma2(w.y, xp[2*p+1], a_hr[c]);
                w = vz[p];
                a_hz[c] = fma2(w.x, xp[2*p], a_hz[c]);
                a_hz[c] = fma2(w.y, xp[2*p+1], a_hz[c]);
                w = vn[p];
                a_hn[c] = fma2(w.x, xp[2*p], a_hn[c]);
                a_hn[c] = fma2(w.y, xp[2*p+1], a_hn[c]);
            }
        }

        const float2 xv = unpack2(xp[oc]);
        float outv[2];
        #pragma unroll
        for (int c = 0; c < 2; c++) {
            const float2 fir = unpack2(a_ir[c]);
            const float2 fiz = unpack2(a_iz[c]);
            const float2 fin = unpack2(a_in[c]);
            const float2 fhr = unpack2(a_hr[c]);
            const float2 fhz = unpack2(a_hz[c]);
            const float2 fhn = unpack2(a_hn[c]);
            const float ir = fir.x + fir.y + s_bih[ob + c];
            const float iz = fiz.x + fiz.y + s_bih[32 + ob + c];
            const float in_ = fin.x + fin.y + s_bih[64 + ob + c];
            const float hr = fhr.x + fhr.y + s_bhh[ob + c];
            const float hz = fhz.x + fhz.y + s_bhh[32 + ob + c];
            const float hn = fhn.x + fhn.y + s_bhh[64 + ob + c];
            const float r = sigmoidf_(ir + hr);
            const float z = sigmoidf_(iz + hz);
            const float nn2 = tanhf(in_ + r * hn);
            const float hp = (c == 0) ? xv.x : xv.y;
            outv[c] = (1.f - z) * nn2 + z * hp;
        }
        if (valid) {
            *(float2*)(xo + (size_t)n * HDIM + ob) = make_float2(outv[0], outv[1]);
        }
    }
}

// ============================================================
// launch
// ============================================================
extern "C" void kernel_launch(void* const* d_in, const int* in_sizes, int n_in,
                              void* d_out, int out_size) {
    const float* x     = (const float*)d_in[0];
    const float* ed    = (const float*)d_in[1];
    const int*   edges = (const int*)d_in[2];
    const int wb = n_in - 8;   // weights are the last 8 inputs
    const float* W1   = (const float*)d_in[wb + 0];
    const float* b1   = (const float*)d_in[wb + 1];
    const float* W2   = (const float*)d_in[wb + 2];
    const float* b2   = (const float*)d_in[wb + 3];
    const float* W_ih = (const float*)d_in[wb + 4];
    const float* W_hh = (const float*)d_in[wb + 5];
    const float* b_ih = (const float*)d_in[wb + 6];
    const float* b_hh = (const float*)d_in[wb + 7];
    float* out = (float*)d_out;

    const int n4 = N_NODES * HDIM / 4;
    const int g4 = (n4 + 255) / 256;

    copy_x_kernel<<<g4, 256>>>(x);
    edge_mlp_kernel<<<N_EDGES / 64, 256>>>(ed, W1, b1, W2, b2);

    const int msg_grid = N_EDGES / 8;                 // warp per edge
    const int gru_grid = (N_NODES + 127) / 128;       // thread per node

    for (int t = 0; t < T_ITERS; t++) {
        msg_kernel<<<msg_grid, 256>>>(edges, t);
        gru_kernel<<<gru_grid, 128>>>(W_ih, W_hh, b_ih, b_hh, out, t);
    }
}